// round 10
// baseline (speedup 1.0000x reference)
#include <cuda_runtime.h>
#include <cstdint>

#define NROWS 8192
#define ROW_BYTES 2048            // 512 floats
#define NBLOCKS 1024
#define NTHREADS 256              // 8 warps, warp-per-row
#define ROWS_PER_BLOCK 8
#define HALF_BYTES (ROWS_PER_BLOCK * ROW_BYTES)   // 16384 B per tensor per block

// Packed accumulator: bits[52:64) block counter, bits[0:52) biased fixed-point
// cosine sum (scale 2^32, bias 2^36/block). Integer adds are exactly
// associative -> deterministic for any atomic order; the atomic's return value
// carries the data -> no __threadfence needed. Self-resets for graph replay.
__device__ unsigned long long g_accum = 0ull;

__device__ __forceinline__ uint32_t smem_u32(const void* p) {
    uint32_t a;
    asm("{ .reg .u64 t; cvta.to.shared.u64 t, %1; cvt.u32.u64 %0, t; }"
        : "=r"(a) : "l"(p));
    return a;
}
__device__ __forceinline__ void mbar_init(uint32_t mbar, uint32_t cnt) {
    asm volatile("mbarrier.init.shared.b64 [%0], %1;" :: "r"(mbar), "r"(cnt) : "memory");
}
__device__ __forceinline__ void mbar_expect_tx(uint32_t mbar, uint32_t bytes) {
    asm volatile("mbarrier.arrive.expect_tx.shared.b64 _, [%0], %1;"
                 :: "r"(mbar), "r"(bytes) : "memory");
}
__device__ __forceinline__ void mbar_wait(uint32_t mbar, uint32_t parity) {
    uint32_t done;
    asm volatile(
        "{\n\t.reg .pred p;\n\t"
        "mbarrier.try_wait.parity.acquire.cta.shared::cta.b64 p, [%1], %2;\n\t"
        "selp.b32 %0, 1, 0, p;\n\t}"
        : "=r"(done) : "r"(mbar), "r"(parity) : "memory");
    if (!done) {
        asm volatile(
            "{\n\t.reg .pred P1;\n\t"
            "WL_%=:\n\t"
            "mbarrier.try_wait.parity.acquire.cta.shared::cta.b64 P1, [%0], %1, 0x989680;\n\t"
            "@P1 bra.uni WD_%=;\n\t"
            "bra.uni WL_%=;\n\t"
            "WD_%=:\n\t}"
            :: "r"(mbar), "r"(parity) : "memory");
    }
}
__device__ __forceinline__ void bulk_copy(uint32_t dst, const void* src,
                                          uint32_t bytes, uint32_t mbar) {
    asm volatile(
        "cp.async.bulk.shared::cluster.global.mbarrier::complete_tx::bytes "
        "[%0], [%1], %2, [%3];"
        :: "r"(dst), "l"(src), "r"(bytes), "r"(mbar) : "memory");
}

__global__ __launch_bounds__(NTHREADS) void byol_tma1_kernel(
    const float* __restrict__ x, const float* __restrict__ xt,
    float* __restrict__ out)
{
    __shared__ __align__(128) unsigned char s_x[HALF_BYTES];
    __shared__ __align__(128) unsigned char s_t[HALF_BYTES];
    __shared__ __align__(8)  unsigned long long s_mbar;
    __shared__ float s_cos[NTHREADS / 32];

    int tid  = threadIdx.x;
    int warp = tid >> 5;
    int lane = tid & 31;

    uint32_t mbar = smem_u32(&s_mbar);

    // Issue the block's whole working set as TWO bulk copies, immediately.
    if (tid == 0) {
        mbar_init(mbar, 1);
        asm volatile("fence.proxy.async.shared::cta;" ::: "memory");
        mbar_expect_tx(mbar, 2 * HALF_BYTES);
        const char* xsrc = (const char*)x  + (size_t)blockIdx.x * HALF_BYTES;
        const char* tsrc = (const char*)xt + (size_t)blockIdx.x * HALF_BYTES;
        bulk_copy(smem_u32(s_x), xsrc, HALF_BYTES, mbar);
        bulk_copy(smem_u32(s_t), tsrc, HALF_BYTES, mbar);
    }
    __syncthreads();          // mbarrier init visible to all warps before wait
    mbar_wait(mbar, 0);       // acquire: SMEM data visible after this

    // Warp 'warp' reduces row 'warp' (conflict-free LDS.128).
    const float4* xr = (const float4*)(s_x + warp * ROW_BYTES);
    const float4* tr = (const float4*)(s_t + warp * ROW_BYTES);

    float4 a0 = xr[lane], a1 = xr[lane + 32], a2 = xr[lane + 64], a3 = xr[lane + 96];
    float4 b0 = tr[lane], b1 = tr[lane + 32], b2 = tr[lane + 64], b3 = tr[lane + 96];

    float dot = 0.f, nx = 0.f, nt = 0.f;
    dot += a0.x*b0.x + a0.y*b0.y + a0.z*b0.z + a0.w*b0.w;
    nx  += a0.x*a0.x + a0.y*a0.y + a0.z*a0.z + a0.w*a0.w;
    nt  += b0.x*b0.x + b0.y*b0.y + b0.z*b0.z + b0.w*b0.w;
    dot += a1.x*b1.x + a1.y*b1.y + a1.z*b1.z + a1.w*b1.w;
    nx  += a1.x*a1.x + a1.y*a1.y + a1.z*a1.z + a1.w*a1.w;
    nt  += b1.x*b1.x + b1.y*b1.y + b1.z*b1.z + b1.w*b1.w;
    dot += a2.x*b2.x + a2.y*b2.y + a2.z*b2.z + a2.w*b2.w;
    nx  += a2.x*a2.x + a2.y*a2.y + a2.z*a2.z + a2.w*a2.w;
    nt  += b2.x*b2.x + b2.y*b2.y + b2.z*b2.z + b2.w*b2.w;
    dot += a3.x*b3.x + a3.y*b3.y + a3.z*b3.z + a3.w*b3.w;
    nx  += a3.x*a3.x + a3.y*a3.y + a3.z*a3.z + a3.w*a3.w;
    nt  += b3.x*b3.x + b3.y*b3.y + b3.z*b3.z + b3.w*b3.w;

    // Warp tree reduction (fixed order -> deterministic).
    #pragma unroll
    for (int off = 16; off > 0; off >>= 1) {
        dot += __shfl_xor_sync(0xffffffffu, dot, off);
        nx  += __shfl_xor_sync(0xffffffffu, nx,  off);
        nt  += __shfl_xor_sync(0xffffffffu, nt,  off);
    }

    if (lane == 0) {
        const float EPS = 1e-8f;
        float denom = fmaxf(sqrtf(nx), EPS) * fmaxf(sqrtf(nt), EPS);
        s_cos[warp] = dot / denom;
    }
    __syncthreads();

    if (tid == 0) {
        // Block partial in double (exact fixed-point conversion).
        double p = 0.0;
        #pragma unroll
        for (int i = 0; i < NTHREADS / 32; i++) p += (double)s_cos[i];

        long long fixed = llrint(p * 4294967296.0);       // * 2^32, |.| < 2^35
        unsigned long long add =
            (1ull << 52) + (unsigned long long)(fixed + (1ll << 36));

        unsigned long long total = atomicAdd(&g_accum, add) + add;

        if ((total >> 52) == (unsigned long long)NBLOCKS) {
            // Last atomic in L2 serialization order: 'total' is the exact sum.
            long long sfix = (long long)(total & ((1ull << 52) - 1))
                           - ((long long)NBLOCKS << 36);   // remove biases
            double cos_sum = (double)sfix * (1.0 / 4294967296.0);
            out[0] = (float)(2.0 - 2.0 * cos_sum / (double)NROWS);
            // All 1024 adds already serialized through L2 -> safe to reset.
            atomicExch(&g_accum, 0ull);
        }
    }
}

extern "C" void kernel_launch(void* const* d_in, const int* in_sizes, int n_in,
                              void* d_out, int out_size)
{
    const float* x  = (const float*)d_in[0];
    const float* xt = (const float*)d_in[1];
    float* out = (float*)d_out;

    byol_tma1_kernel<<<NBLOCKS, NTHREADS>>>(x, xt, out);
}

// round 11
// speedup vs baseline: 1.2657x; 1.2657x over previous
#include <cuda_runtime.h>
#include <cstdint>

#define NROWS 8192
#define D4 128              // 512 floats = 128 float4 per row
#define NBLOCKS 512
#define NTHREADS 256
#define WARPS_PER_BLK 8
#define ROWS_PER_WARP 2     // 512 * 8 * 2 = 8192 rows

// Packed accumulator: bits[52:64) block counter (<=512), bits[0:52) biased
// fixed-point cosine sum (scale 2^32, bias 2^37/block). Integer adds are
// exactly associative -> deterministic for any atomic order; the atomic's
// return value carries the data -> no __threadfence. Self-resets for replay.
__device__ unsigned long long g_accum = 0ull;

// Un-sinkable 128-bit load: volatile asm pins mutual order of loads (they all
// issue as one front batch) while remaining hoistable past non-volatile math.
__device__ __forceinline__ float4 ldg128(const float4* p) {
    float4 v;
    asm volatile("ld.global.nc.v4.f32 {%0,%1,%2,%3}, [%4];"
                 : "=f"(v.x), "=f"(v.y), "=f"(v.z), "=f"(v.w)
                 : "l"(p));
    return v;
}

__device__ __forceinline__ void row_accum(
    const float4& a0, const float4& a1, const float4& a2, const float4& a3,
    const float4& b0, const float4& b1, const float4& b2, const float4& b3,
    float& dot, float& nx, float& nt)
{
    dot += a0.x*b0.x + a0.y*b0.y + a0.z*b0.z + a0.w*b0.w;
    nx  += a0.x*a0.x + a0.y*a0.y + a0.z*a0.z + a0.w*a0.w;
    nt  += b0.x*b0.x + b0.y*b0.y + b0.z*b0.z + b0.w*b0.w;
    dot += a1.x*b1.x + a1.y*b1.y + a1.z*b1.z + a1.w*b1.w;
    nx  += a1.x*a1.x + a1.y*a1.y + a1.z*a1.z + a1.w*a1.w;
    nt  += b1.x*b1.x + b1.y*b1.y + b1.z*b1.z + b1.w*b1.w;
    dot += a2.x*b2.x + a2.y*b2.y + a2.z*b2.z + a2.w*b2.w;
    nx  += a2.x*a2.x + a2.y*a2.y + a2.z*a2.z + a2.w*a2.w;
    nt  += b2.x*b2.x + b2.y*b2.y + b2.z*b2.z + b2.w*b2.w;
    dot += a3.x*b3.x + a3.y*b3.y + a3.z*b3.z + a3.w*b3.w;
    nx  += a3.x*a3.x + a3.y*a3.y + a3.z*a3.z + a3.w*a3.w;
    nt  += b3.x*b3.x + b3.y*b3.y + b3.z*b3.z + b3.w*b3.w;
}

__global__ __launch_bounds__(NTHREADS, 4) void byol_kernel(
    const float4* __restrict__ x, const float4* __restrict__ xt,
    float* __restrict__ out)
{
    __shared__ float s_cos[WARPS_PER_BLK];

    int warp = threadIdx.x >> 5;
    int lane = threadIdx.x & 31;
    int row0 = (blockIdx.x * WARPS_PER_BLK + warp) * ROWS_PER_WARP;

    const float4* xr = x  + (size_t)row0 * D4 + lane;
    const float4* tr = xt + (size_t)row0 * D4 + lane;

    // Row 0: batch 8 independent LDG.128s.
    float4 a0 = ldg128(xr +   0), a1 = ldg128(xr +  32),
           a2 = ldg128(xr +  64), a3 = ldg128(xr +  96);
    float4 b0 = ldg128(tr +   0), b1 = ldg128(tr +  32),
           b2 = ldg128(tr +  64), b3 = ldg128(tr +  96);

    // Row 1: batch its 8 loads too (volatile order: after row0's loads, but
    // free to issue before row0's arithmetic -> up to 16 in flight).
    float4 c0 = ldg128(xr + 128), c1 = ldg128(xr + 160),
           c2 = ldg128(xr + 192), c3 = ldg128(xr + 224);
    float4 d0 = ldg128(tr + 128), d1 = ldg128(tr + 160),
           d2 = ldg128(tr + 192), d3 = ldg128(tr + 224);

    float dot0 = 0.f, nx0 = 0.f, nt0 = 0.f;
    row_accum(a0, a1, a2, a3, b0, b1, b2, b3, dot0, nx0, nt0);
    float dot1 = 0.f, nx1 = 0.f, nt1 = 0.f;
    row_accum(c0, c1, c2, c3, d0, d1, d2, d3, dot1, nx1, nt1);

    // Warp tree reductions (fixed order -> deterministic).
    #pragma unroll
    for (int off = 16; off > 0; off >>= 1) {
        dot0 += __shfl_xor_sync(0xffffffffu, dot0, off);
        nx0  += __shfl_xor_sync(0xffffffffu, nx0,  off);
        nt0  += __shfl_xor_sync(0xffffffffu, nt0,  off);
        dot1 += __shfl_xor_sync(0xffffffffu, dot1, off);
        nx1  += __shfl_xor_sync(0xffffffffu, nx1,  off);
        nt1  += __shfl_xor_sync(0xffffffffu, nt1,  off);
    }

    if (lane == 0) {
        const float EPS = 1e-8f;
        float den0 = fmaxf(sqrtf(nx0), EPS) * fmaxf(sqrtf(nt0), EPS);
        float den1 = fmaxf(sqrtf(nx1), EPS) * fmaxf(sqrtf(nt1), EPS);
        s_cos[warp] = dot0 / den0 + dot1 / den1;
    }
    __syncthreads();

    if (threadIdx.x == 0) {
        // Block partial in double (exact fixed-point conversion).
        double p = 0.0;
        #pragma unroll
        for (int i = 0; i < WARPS_PER_BLK; i++) p += (double)s_cos[i];

        long long fixed = llrint(p * 4294967296.0);       // * 2^32, |.| < 2^37
        unsigned long long add =
            (1ull << 52) + (unsigned long long)(fixed + (1ll << 37));

        unsigned long long total = atomicAdd(&g_accum, add) + add;

        if ((total >> 52) == (unsigned long long)NBLOCKS) {
            // Last atomic in L2 serialization order: 'total' is the exact sum.
            long long sfix = (long long)(total & ((1ull << 52) - 1))
                           - ((long long)NBLOCKS << 37);   // remove biases
            double cos_sum = (double)sfix * (1.0 / 4294967296.0);
            out[0] = (float)(2.0 - 2.0 * cos_sum / (double)NROWS);
            // All 512 adds already serialized through L2 -> safe to reset.
            atomicExch(&g_accum, 0ull);
        }
    }
}

extern "C" void kernel_launch(void* const* d_in, const int* in_sizes, int n_in,
                              void* d_out, int out_size)
{
    const float4* x  = (const float4*)d_in[0];
    const float4* xt = (const float4*)d_in[1];
    float* out = (float*)d_out;

    byol_kernel<<<NBLOCKS, NTHREADS>>>(x, xt, out);
}